// round 1
// baseline (speedup 1.0000x reference)
#include <cuda_runtime.h>
#include <cstdint>
#include <math.h>

#define BATCH 256
#define SEQ   256
#define NIN   512
#define HD    1024
#define H4    4096
#define MOUT  512

// GEMM tiling
#define BM 64
#define BN 128
#define BK 32
#define PAD 4

// ---------------------------------------------------------------------------
// Scratch (device globals; no allocation in kernel_launch)
// ---------------------------------------------------------------------------
__device__ float g_pre[(size_t)BATCH * SEQ * H4];  // [b][s][4H]  (1 GiB)
__device__ float g_z[BATCH * H4];                  // per-step z = h @ Wh^T
__device__ float g_h[2][BATCH * HD];               // ping-pong hidden state
__device__ float g_c[BATCH * HD];                  // cell state

// ---------------------------------------------------------------------------
// Helpers
// ---------------------------------------------------------------------------
__device__ __forceinline__ uint32_t f2tf32(float x) {
    uint32_t u;
    asm("cvt.rna.tf32.f32 %0, %1;" : "=r"(u) : "f"(x));
    return u;
}

__device__ __forceinline__ void mma_tf32(float d[4], const uint32_t a[4],
                                         const uint32_t b[2]) {
    asm volatile(
        "mma.sync.aligned.m16n8k8.row.col.f32.tf32.tf32.f32 "
        "{%0,%1,%2,%3}, {%4,%5,%6,%7}, {%8,%9}, {%0,%1,%2,%3};\n"
        : "+f"(d[0]), "+f"(d[1]), "+f"(d[2]), "+f"(d[3])
        : "r"(a[0]), "r"(a[1]), "r"(a[2]), "r"(a[3]), "r"(b[0]), "r"(b[1]));
}

struct GemmArgs {
    const float* A;        // [M, K] row-major contiguous
    const float* B[4];     // per-gate weights, each [n_per_gate, K] row-major
    const float* bias[4];  // per-gate bias (or nullptr)
    float* C;              // [M, N] row-major
    int M, N, K, n_per_gate;
};

// ---------------------------------------------------------------------------
// Generic tf32 GEMM: C = A @ B^T (+bias). Requires M%64==0, N%128==0, K%32==0,
// and BN (=128) must divide n_per_gate so a block stays within one gate.
// 256 threads, 8 warps in 2x4 layout; warp tile 32x32 via 2x4 m16n8k8 mmas.
// ---------------------------------------------------------------------------
__global__ __launch_bounds__(256, 2)
void gemm_tf32_kernel(GemmArgs args) {
    __shared__ uint32_t sA[BM][BK + PAD];
    __shared__ uint32_t sB[BN][BK + PAD];

    const int tid  = threadIdx.x;
    const int lane = tid & 31;
    const int warp = tid >> 5;
    const int wm   = warp >> 2;   // 0..1
    const int wn   = warp & 3;    // 0..3
    const int lr   = lane >> 2;   // 0..7
    const int lc   = lane & 3;    // 0..3

    const int m0 = blockIdx.y * BM;
    const int n0 = blockIdx.x * BN;

    const int gate = n0 / args.n_per_gate;
    const float* __restrict__ Bp = args.B[gate];
    const int jn0 = n0 - gate * args.n_per_gate;
    const int K = args.K;
    const int K4 = K >> 2;

    const float4* __restrict__ A4 = reinterpret_cast<const float4*>(args.A);
    const float4* __restrict__ B4 = reinterpret_cast<const float4*>(Bp);

    float4 pa[2], pb[4];

    auto loadA = [&](int k0) {
#pragma unroll
        for (int j = 0; j < 2; j++) {
            int i = tid + 256 * j;
            int r = i >> 3, c = i & 7;  // 8 float4 per 32-wide row
            pa[j] = A4[(size_t)(m0 + r) * K4 + (k0 >> 2) + c];
        }
    };
    auto loadB = [&](int k0) {
#pragma unroll
        for (int j = 0; j < 4; j++) {
            int i = tid + 256 * j;
            int r = i >> 3, c = i & 7;
            pb[j] = B4[(size_t)(jn0 + r) * K4 + (k0 >> 2) + c];
        }
    };
    auto stage = [&]() {
#pragma unroll
        for (int j = 0; j < 2; j++) {
            int i = tid + 256 * j;
            int r = i >> 3, c = i & 7;
            sA[r][c * 4 + 0] = f2tf32(pa[j].x);
            sA[r][c * 4 + 1] = f2tf32(pa[j].y);
            sA[r][c * 4 + 2] = f2tf32(pa[j].z);
            sA[r][c * 4 + 3] = f2tf32(pa[j].w);
        }
#pragma unroll
        for (int j = 0; j < 4; j++) {
            int i = tid + 256 * j;
            int r = i >> 3, c = i & 7;
            sB[r][c * 4 + 0] = f2tf32(pb[j].x);
            sB[r][c * 4 + 1] = f2tf32(pb[j].y);
            sB[r][c * 4 + 2] = f2tf32(pb[j].z);
            sB[r][c * 4 + 3] = f2tf32(pb[j].w);
        }
    };

    float acc[2][4][4];
#pragma unroll
    for (int mt = 0; mt < 2; mt++)
#pragma unroll
        for (int nt = 0; nt < 4; nt++)
#pragma unroll
            for (int e = 0; e < 4; e++) acc[mt][nt][e] = 0.0f;

    loadA(0);
    loadB(0);
    stage();
    __syncthreads();

    const int nk = K / BK;
    for (int t = 0; t < nk; t++) {
        if (t + 1 < nk) {          // prefetch next tile into registers
            loadA((t + 1) * BK);
            loadB((t + 1) * BK);
        }
#pragma unroll
        for (int kk = 0; kk < BK; kk += 8) {
            uint32_t a[2][4], b[4][2];
#pragma unroll
            for (int mt = 0; mt < 2; mt++) {
                int mb = wm * 32 + mt * 16;
                a[mt][0] = sA[mb + lr][kk + lc];
                a[mt][1] = sA[mb + 8 + lr][kk + lc];
                a[mt][2] = sA[mb + lr][kk + 4 + lc];
                a[mt][3] = sA[mb + 8 + lr][kk + 4 + lc];
            }
#pragma unroll
            for (int nt = 0; nt < 4; nt++) {
                int nb = wn * 32 + nt * 8;
                b[nt][0] = sB[nb + lr][kk + lc];
                b[nt][1] = sB[nb + lr][kk + 4 + lc];
            }
#pragma unroll
            for (int mt = 0; mt < 2; mt++)
#pragma unroll
                for (int nt = 0; nt < 4; nt++) mma_tf32(acc[mt][nt], a[mt], b[nt]);
        }
        __syncthreads();
        if (t + 1 < nk) {
            stage();
            __syncthreads();
        }
    }

    // Epilogue: c0:(r, c) c1:(r, c+1) c2:(r+8, c) c3:(r+8, c+1)
    const float* bp = args.bias[gate];
    const int N = args.N;
#pragma unroll
    for (int mt = 0; mt < 2; mt++) {
#pragma unroll
        for (int nt = 0; nt < 4; nt++) {
            int r = m0 + wm * 32 + mt * 16 + lr;
            int cidx = n0 + wn * 32 + nt * 8 + lc * 2;
            float bv0 = 0.0f, bv1 = 0.0f;
            if (bp) {
                int jc = cidx - gate * args.n_per_gate;
                bv0 = bp[jc];
                bv1 = bp[jc + 1];
            }
            float* C0 = args.C + (size_t)r * N;
            float* C1 = args.C + (size_t)(r + 8) * N;
            C0[cidx]     = acc[mt][nt][0] + bv0;
            C0[cidx + 1] = acc[mt][nt][1] + bv1;
            C1[cidx]     = acc[mt][nt][2] + bv0;
            C1[cidx + 1] = acc[mt][nt][3] + bv1;
        }
    }
}

// ---------------------------------------------------------------------------
// Pointwise LSTM gate update:
//   z_total = g_z (h@Wh^T) + g_pre (x@Wx^T + bx)
//   g=tanh, i/f/o=sigmoid; c = g*i + c*f; h = tanh(c)*o
// ---------------------------------------------------------------------------
__global__ void lstm_gates_kernel(int t, int out_buf) {
    int idx = blockIdx.x * blockDim.x + threadIdx.x;  // 0 .. BATCH*HD-1
    int b = idx >> 10;
    int j = idx & (HD - 1);
    const float* __restrict__ z = g_z + (size_t)b * H4;
    const float* __restrict__ p = g_pre + ((size_t)b * SEQ + t) * H4;

    float zg = z[j]          + p[j];
    float zi = z[j + HD]     + p[j + HD];
    float zf = z[j + 2 * HD] + p[j + 2 * HD];
    float zo = z[j + 3 * HD] + p[j + 3 * HD];

    float gg = tanhf(zg);
    float ii = 1.0f / (1.0f + expf(-zi));
    float ff = 1.0f / (1.0f + expf(-zf));
    float oo = 1.0f / (1.0f + expf(-zo));

    float cn = gg * ii + g_c[idx] * ff;
    g_c[idx] = cn;
    g_h[out_buf][idx] = tanhf(cn) * oo;
}

__global__ void zero_state_kernel() {
    int idx = blockIdx.x * blockDim.x + threadIdx.x;
    if (idx < BATCH * HD) {
        g_h[0][idx] = 0.0f;
        g_c[idx] = 0.0f;
    }
}

// ---------------------------------------------------------------------------
// Driver
// ---------------------------------------------------------------------------
extern "C" void kernel_launch(void* const* d_in, const int* in_sizes, int n_in,
                              void* d_out, int out_size) {
    const float* x    = (const float*)d_in[0];
    const float* Wgx  = (const float*)d_in[1];
    const float* bgx  = (const float*)d_in[2];
    const float* Wgh  = (const float*)d_in[3];
    const float* Wix  = (const float*)d_in[4];
    const float* bix  = (const float*)d_in[5];
    const float* Wih  = (const float*)d_in[6];
    const float* Wfx  = (const float*)d_in[7];
    const float* bfx  = (const float*)d_in[8];
    const float* Wfh  = (const float*)d_in[9];
    const float* Wox  = (const float*)d_in[10];
    const float* box_ = (const float*)d_in[11];
    const float* Woh  = (const float*)d_in[12];
    const float* Wp   = (const float*)d_in[13];
    const float* bpb  = (const float*)d_in[14];
    float* out = (float*)d_out;

    float *pre_ptr, *z_ptr, *h_ptr;
    cudaGetSymbolAddress((void**)&pre_ptr, g_pre);
    cudaGetSymbolAddress((void**)&z_ptr, g_z);
    cudaGetSymbolAddress((void**)&h_ptr, g_h);

    zero_state_kernel<<<(BATCH * HD + 255) / 256, 256>>>();

    // Input projection: pre[b][s][4H] = x[b][s][:] @ Wx^T + bx
    // x viewed as [BATCH*SEQ, NIN] row-major (m = b*SEQ + s).
    {
        GemmArgs a;
        a.A = x;
        a.B[0] = Wgx; a.B[1] = Wix; a.B[2] = Wfx; a.B[3] = Wox;
        a.bias[0] = bgx; a.bias[1] = bix; a.bias[2] = bfx; a.bias[3] = box_;
        a.C = pre_ptr;
        a.M = BATCH * SEQ; a.N = H4; a.K = NIN; a.n_per_gate = HD;
        gemm_tf32_kernel<<<dim3(H4 / BN, (BATCH * SEQ) / BM), 256>>>(a);
    }

    // Recurrence: 256 steps of z = h@Wh^T then gate pointwise.
    for (int t = 0; t < SEQ; t++) {
        GemmArgs a;
        a.A = h_ptr + (size_t)(t & 1) * (BATCH * HD);
        a.B[0] = Wgh; a.B[1] = Wih; a.B[2] = Wfh; a.B[3] = Woh;
        a.bias[0] = a.bias[1] = a.bias[2] = a.bias[3] = nullptr;
        a.C = z_ptr;
        a.M = BATCH; a.N = H4; a.K = HD; a.n_per_gate = HD;
        gemm_tf32_kernel<<<dim3(H4 / BN, BATCH / BM), 256>>>(a);

        lstm_gates_kernel<<<(BATCH * HD) / 256, 256>>>(t, (t + 1) & 1);
    }

    // Final projection: out = h_final @ Wp^T + bp   (h_final lives in g_h[0])
    {
        GemmArgs a;
        a.A = h_ptr;  // buffer 0 after the last step
        a.B[0] = a.B[1] = a.B[2] = a.B[3] = Wp;
        a.bias[0] = a.bias[1] = a.bias[2] = a.bias[3] = bpb;
        a.C = out;
        a.M = BATCH; a.N = MOUT; a.K = HD; a.n_per_gate = MOUT;
        gemm_tf32_kernel<<<dim3(MOUT / BN, BATCH / BM), 256>>>(a);
    }
}